// round 16
// baseline (speedup 1.0000x reference)
#include <cuda_runtime.h>
#include <math.h>

// Problem constants (fixed shapes per reference)
#define Bg   64
#define Nn   1024
#define TOT  65536      // Bg*Nn
#define NE   2097152
#define INC  128
#define HID  32
#define KK   16
#define OUTC 10

// ---------------- device scratch (no allocation allowed) ----------------
__device__ float d_h1[TOT * HID];      // after lin1
__device__ float d_h [TOT * HID];      // after conv1
__device__ float d_s [TOT * KK];       // softmax assignments
__device__ int   d_deg[TOT];           // out-degree == d_flat
__device__ int   d_rowstart[TOT];
__device__ int   d_cursor[TOT];
__device__ int   d_csr[NE];            // dst sorted by src (CSR)
__device__ int   d_bsum[64];           // per-block degree totals for scan
__device__ float d_outp[Bg * KK * HID];   // s^T h
__device__ float d_oadj[Bg * KK * KK];    // s^T adj s
__device__ float d_ssg [Bg * KK * KK];    // s^T s
__device__ float d_den [Bg];              // sum d*s^2

__device__ __forceinline__ float warp_sum(float v) {
    #pragma unroll
    for (int o = 16; o; o >>= 1) v += __shfl_xor_sync(0xffffffffu, v, o);
    return v;
}

// ---------------- zero scratch + output ----------------
__global__ void k_zero(float* __restrict__ out) {
    int i = blockIdx.x * blockDim.x + threadIdx.x;   // 256*256 = 65536
    d_deg[i] = 0;
    if (i < Bg * KK * HID) d_outp[i] = 0.f;
    if (i < Bg * KK * KK)  { d_oadj[i] = 0.f; d_ssg[i] = 0.f; }
    if (i < Bg)            d_den[i] = 0.f;
    if (i < Bg * OUTC + 2) out[i] = 0.f;
}

// ---------------- degree histogram over src (8 edges/thread) --------
__global__ void k_hist(const int4* __restrict__ ei4) {
    int i = blockIdx.x * blockDim.x + threadIdx.x;   // NE/8 = 262144 threads
    int4 a = ei4[i];
    int4 b = ei4[i + NE / 8];
    atomicAdd(&d_deg[a.x], 1);
    atomicAdd(&d_deg[a.y], 1);
    atomicAdd(&d_deg[a.z], 1);
    atomicAdd(&d_deg[a.w], 1);
    atomicAdd(&d_deg[b.x], 1);
    atomicAdd(&d_deg[b.y], 1);
    atomicAdd(&d_deg[b.z], 1);
    atomicAdd(&d_deg[b.w], 1);
}

// ---------------- parallel exclusive scan of 65536 degrees ----------------
__global__ void k_scan1() {
    __shared__ int wsum[32];
    int b = blockIdx.x, tid = threadIdx.x;
    int idx = b * 1024 + tid;
    int v = d_deg[idx];
    int lane = tid & 31, wid = tid >> 5;
    int p = v;
    #pragma unroll
    for (int o = 1; o < 32; o <<= 1) {
        int t = __shfl_up_sync(0xffffffffu, p, o);
        if (lane >= o) p += t;
    }
    if (lane == 31) wsum[wid] = p;
    __syncthreads();
    if (wid == 0) {
        int w = wsum[lane];
        #pragma unroll
        for (int o = 1; o < 32; o <<= 1) {
            int t = __shfl_up_sync(0xffffffffu, w, o);
            if (lane >= o) w += t;
        }
        wsum[lane] = w;
    }
    __syncthreads();
    int ex = p - v + (wid ? wsum[wid - 1] : 0);
    d_rowstart[idx] = ex;
    if (tid == 1023) d_bsum[b] = ex + v;
}

__global__ void k_scan2() {
    __shared__ int w0;
    int t = threadIdx.x;                       // 64 threads
    int v = d_bsum[t];
    int lane = t & 31, wid = t >> 5;
    int p = v;
    #pragma unroll
    for (int o = 1; o < 32; o <<= 1) {
        int x = __shfl_up_sync(0xffffffffu, p, o);
        if (lane >= o) p += x;
    }
    if (t == 31) w0 = p;
    __syncthreads();
    d_bsum[t] = p - v + (wid ? w0 : 0);
}

__global__ void k_scan3() {
    int idx = blockIdx.x * 1024 + threadIdx.x;
    int r = d_rowstart[idx] + d_bsum[blockIdx.x];
    d_rowstart[idx] = r;
    d_cursor[idx]   = r;
}

// ---------------- scatter dst into CSR (8 edges/thread) -------------
__global__ void k_scatter(const int* __restrict__ ei) {
    const int4* src4 = (const int4*)ei;
    const int4* dst4 = (const int4*)(ei + NE);
    int i = blockIdx.x * blockDim.x + threadIdx.x;   // NE/8 threads
    int4 s0 = src4[i];
    int4 s1 = src4[i + NE / 8];
    int4 d0 = dst4[i];
    int4 d1 = dst4[i + NE / 8];
    d_csr[atomicAdd(&d_cursor[s0.x], 1)] = d0.x;
    d_csr[atomicAdd(&d_cursor[s0.y], 1)] = d0.y;
    d_csr[atomicAdd(&d_cursor[s0.z], 1)] = d0.z;
    d_csr[atomicAdd(&d_cursor[s0.w], 1)] = d0.w;
    d_csr[atomicAdd(&d_cursor[s1.x], 1)] = d1.x;
    d_csr[atomicAdd(&d_cursor[s1.y], 1)] = d1.y;
    d_csr[atomicAdd(&d_cursor[s1.z], 1)] = d1.z;
    d_csr[atomicAdd(&d_cursor[s1.w], 1)] = d1.w;
}

// ---------------- h1 = x @ W1^T + b1 ----------------
__global__ void k_lin1(const float4* __restrict__ x4,
                       const float4* __restrict__ W1f4,
                       const float*  __restrict__ b1) {
    __shared__ float4 Wf[32 * 32];   // [c4][o]
    __shared__ float  bs[32];
    int tid = threadIdx.x;
    for (int i = tid; i < 1024; i += 256) {
        int o = i & 31, c4 = i >> 5;
        Wf[c4 * 32 + o] = W1f4[o * 32 + c4];
    }
    if (tid < 32) bs[tid] = b1[tid];
    __syncthreads();
    int w = tid >> 5, lane = tid & 31;
    int nb = (blockIdx.x * 8 + w) * 4;   // 4 nodes per warp
    float a0 = bs[lane], a1 = a0, a2 = a0, a3 = a0;
    const float4* x0 = x4 + (size_t)nb * 32;
    #pragma unroll 8
    for (int c4 = 0; c4 < 32; c4++) {
        float4 wv = Wf[c4 * 32 + lane];
        float4 xa = x0[c4], xb = x0[32 + c4], xc = x0[64 + c4], xd = x0[96 + c4];
        a0 += xa.x * wv.x + xa.y * wv.y + xa.z * wv.z + xa.w * wv.w;
        a1 += xb.x * wv.x + xb.y * wv.y + xb.z * wv.z + xb.w * wv.w;
        a2 += xc.x * wv.x + xc.y * wv.y + xc.z * wv.z + xc.w * wv.w;
        a3 += xd.x * wv.x + xd.y * wv.y + xd.z * wv.z + xd.w * wv.w;
    }
    d_h1[(nb + 0) * 32 + lane] = a0;
    d_h1[(nb + 1) * 32 + lane] = a1;
    d_h1[(nb + 2) * 32 + lane] = a2;
    d_h1[(nb + 3) * 32 + lane] = a3;
}

// ---------------- conv1 + pool-projection + softmax (fused, warp/node) ------
// Gather: per-subgroup direct index loads, software-pipelined one iteration
// ahead so index loads overlap the gathers (breaks the 2-deep L2 chain).
__global__ void k_conv(const float* __restrict__ Wrel1, const float* __restrict__ brel1,
                       const float* __restrict__ Wroot1, const float* __restrict__ Wp,
                       const float* __restrict__ bp) {
    __shared__ float Wr[1024], Wo[1024], Wpt[512], br[32], bps[16];
    __shared__ __align__(16) float stage[8][64];
    int tid = threadIdx.x;
    for (int i = tid; i < 1024; i += 256) {
        int o = i >> 5, c = i & 31;
        Wr[c * 32 + o] = Wrel1[i];
        Wo[c * 32 + o] = Wroot1[i];
    }
    for (int i = tid; i < 512; i += 256) {
        int k = i >> 5, o = i & 31;
        Wpt[o * 16 + k] = Wp[i];
    }
    if (tid < 32) br[tid]  = brel1[tid];
    if (tid < 16) bps[tid] = bp[tid];
    __syncthreads();
    const float4* h1f4 = (const float4*)d_h1;
    int w = tid >> 5, lane = tid & 31;
    int qg = lane >> 3;            // neighbor subgroup 0..3
    int qc = lane & 7;             // float4 column 0..7
    int gw = blockIdx.x * 8 + w;   // 8192 warps, 8 nodes each
    for (int i = 0; i < 8; i++) {
        int n = gw * 8 + i;
        float h1c = d_h1[n * 32 + lane];
        int st = d_rowstart[n], len = d_deg[n];
        float4 a0 = {0.f,0.f,0.f,0.f}, a1 = {0.f,0.f,0.f,0.f};
        int j = qg;
        int eA = (j     < len) ? d_csr[st + j]     : -1;
        int eB = (j + 4 < len) ? d_csr[st + j + 4] : -1;
        while (eA >= 0) {
            int jn = j + 8;
            int nA = (jn     < len) ? d_csr[st + jn]     : -1;  // prefetch next
            int nB = (jn + 4 < len) ? d_csr[st + jn + 4] : -1;
            float4 v0 = h1f4[eA * 8 + qc];
            a0.x += v0.x; a0.y += v0.y; a0.z += v0.z; a0.w += v0.w;
            if (eB >= 0) {
                float4 v1 = h1f4[eB * 8 + qc];
                a1.x += v1.x; a1.y += v1.y; a1.z += v1.z; a1.w += v1.w;
            }
            eA = nA; eB = nB; j = jn;
        }
        a0.x += a1.x; a0.y += a1.y; a0.z += a1.z; a0.w += a1.w;
        #pragma unroll
        for (int o = 8; o <= 16; o <<= 1) {     // reduce over 4 subgroups
            a0.x += __shfl_xor_sync(0xffffffffu, a0.x, o);
            a0.y += __shfl_xor_sync(0xffffffffu, a0.y, o);
            a0.z += __shfl_xor_sync(0xffffffffu, a0.z, o);
            a0.w += __shfl_xor_sync(0xffffffffu, a0.w, o);
        }
        __syncwarp();
        if (qg == 0) ((float4*)&stage[w][0])[qc] = a0;   // cols 0..31 = neighbor sum
        stage[w][32 + lane] = h1c;
        __syncwarp();
        float hv = br[lane];
        #pragma unroll
        for (int c = 0; c < 32; c++)
            hv += stage[w][c] * Wr[c * 32 + lane] + stage[w][32 + c] * Wo[c * 32 + lane];
        d_h[n * 32 + lane] = hv;
        __syncwarp();
        stage[w][lane] = hv;
        __syncwarp();
        int k = lane & 15;                 // duplicated halves
        float p = bps[k];
        #pragma unroll
        for (int o = 0; o < 32; o++) p += stage[w][o] * Wpt[o * 16 + k];
        float m = p;
        #pragma unroll
        for (int off = 8; off >= 1; off >>= 1)
            m = fmaxf(m, __shfl_xor_sync(0xffffffffu, m, off));
        float e = __expf(p - m);
        float se = e;
        #pragma unroll
        for (int off = 8; off >= 1; off >>= 1)
            se += __shfl_xor_sync(0xffffffffu, se, off);
        if (lane < 16) d_s[n * 16 + lane] = e / se;
    }
}

// ---------------- adj@s gather + per-graph reductions (register accumulators) ----
// Gather software-pipelined one iteration ahead, same as conv.
__global__ void k_pool() {
    __shared__ float wacc[8][1056];
    __shared__ __align__(16) float sst[8][16], ast[8][16];
    int tid = threadIdx.x;
    int w = tid >> 5, lane = tid & 31;
    int g = blockIdx.x >> 3;
    int nb = g * 1024 + (blockIdx.x & 7) * 128 + w * 16;   // 16 nodes per warp
    int c = lane & 15;
    int qg = lane >> 2;            // neighbor subgroup 0..7
    int qc = lane & 3;             // float4 column 0..3
    const float4* sf4 = (const float4*)d_s;
    float rout[16], radj[16], rss[16];
    #pragma unroll
    for (int k = 0; k < 16; k++) { rout[k] = 0.f; radj[k] = 0.f; rss[k] = 0.f; }
    float denp = 0.f;
    for (int i = 0; i < 16; i++) {
        int n = nb + i;
        float sv = d_s[n * 16 + c];
        int st = d_rowstart[n], len = d_deg[n];
        float4 a0 = {0.f,0.f,0.f,0.f}, a1 = {0.f,0.f,0.f,0.f};
        int j = qg;
        int eA = (j     < len) ? d_csr[st + j]     : -1;
        int eB = (j + 8 < len) ? d_csr[st + j + 8] : -1;
        while (eA >= 0) {
            int jn = j + 16;
            int nA = (jn     < len) ? d_csr[st + jn]     : -1;  // prefetch next
            int nB = (jn + 8 < len) ? d_csr[st + jn + 8] : -1;
            float4 v0 = sf4[eA * 4 + qc];
            a0.x += v0.x; a0.y += v0.y; a0.z += v0.z; a0.w += v0.w;
            if (eB >= 0) {
                float4 v1 = sf4[eB * 4 + qc];
                a1.x += v1.x; a1.y += v1.y; a1.z += v1.z; a1.w += v1.w;
            }
            eA = nA; eB = nB; j = jn;
        }
        a0.x += a1.x; a0.y += a1.y; a0.z += a1.z; a0.w += a1.w;
        #pragma unroll
        for (int o = 4; o <= 16; o <<= 1) {     // reduce over 8 subgroups
            a0.x += __shfl_xor_sync(0xffffffffu, a0.x, o);
            a0.y += __shfl_xor_sync(0xffffffffu, a0.y, o);
            a0.z += __shfl_xor_sync(0xffffffffu, a0.z, o);
            a0.w += __shfl_xor_sync(0xffffffffu, a0.w, o);
        }
        float hl = d_h[n * 32 + lane];
        __syncwarp();
        if (lane < 4) ((float4*)&ast[w][0])[qc] = a0;   // adj@s row (16 floats)
        if (lane < 16) sst[w][lane] = sv;
        __syncwarp();
        float av = (lane < 16) ? ast[w][lane] : 0.f;
        #pragma unroll
        for (int k = 0; k < 16; k++) {
            float sk = sst[w][k];
            rout[k] += sk * hl;
            radj[k] += sk * av;
            rss[k]  += sk * sv;
        }
        if (lane < 16) denp += (float)len * sv * sv;
        __syncwarp();
    }
    float* wa = wacc[w];
    #pragma unroll
    for (int k = 0; k < 16; k++) wa[k * 32 + lane] = rout[k];
    if (lane < 16) {
        #pragma unroll
        for (int k = 0; k < 16; k++) {
            wa[512 + k * 16 + lane] = radj[k];
            wa[768 + k * 16 + lane] = rss[k];
        }
    }
    float dv = (lane < 16) ? denp : 0.f;
    dv = warp_sum(dv);
    if (lane == 0) wa[1024] = dv;
    __syncthreads();
    for (int idx = tid; idx < 1025; idx += 256) {
        float v = 0.f;
        #pragma unroll
        for (int ww = 0; ww < 8; ww++) v += wacc[ww][idx];
        if (idx < 512)       atomicAdd(&d_outp[g * 512 + idx], v);
        else if (idx < 768)  atomicAdd(&d_oadj[g * 256 + (idx - 512)], v);
        else if (idx < 1024) atomicAdd(&d_ssg [g * 256 + (idx - 768)], v);
        else                 atomicAdd(&d_den[g], v);
    }
}

// ---------------- per-graph tail ----------------
__global__ void k_final(const float* __restrict__ Wrel2, const float* __restrict__ brel2,
                        const float* __restrict__ Wroot2, const float* __restrict__ W2,
                        const float* __restrict__ b2, const float* __restrict__ W3,
                        const float* __restrict__ b3, float* __restrict__ out) {
    int g = blockIdx.x, t = threadIdx.x;   // 32 threads
    __shared__ float A[256], S[256], O[512], di[16], u[16];
    __shared__ float tm[32], vm[32], gm[32], zm[32], lg[10], bc[2];
    for (int i = t; i < 256; i += 32) { A[i] = d_oadj[g * 256 + i]; S[i] = d_ssg[g * 256 + i]; }
    for (int i = t; i < 512; i += 32)   O[i] = d_outp[g * 512 + i];
    __syncwarp();
    float num = (t < 16) ? A[t * 17] : 0.f;
    num = warp_sum(num);
    float den = d_den[g];
    float p2 = 0.f;
    for (int i = t; i < 256; i += 32) p2 += S[i] * S[i];
    float nrm = sqrtf(warp_sum(p2));
    float p3 = 0.f;
    for (int i = t; i < 256; i += 32) {
        float dvv = S[i] / nrm - (((i >> 4) == (i & 15)) ? 0.25f : 0.f);
        p3 += dvv * dvv;
    }
    float ortho = sqrtf(warp_sum(p3));
    if (t == 0) {
        atomicAdd(out + Bg * OUTC,     -(num / den) * (1.f / Bg));
        atomicAdd(out + Bg * OUTC + 1, ortho * (1.f / Bg));
    }
    if (t < 16) A[t * 17] = 0.f;
    __syncwarp();
    if (t < 16) {
        float r = 0.f;
        for (int j = 0; j < 16; j++) r += A[t * 16 + j];
        di[t] = sqrtf(r) + 1e-15f;
    }
    __syncwarp();
    if (t < 16) {
        float uu = 0.f;
        for (int k = 0; k < 16; k++) uu += A[k * 16 + t] / di[k];
        u[t] = uu / di[t];
    }
    __syncwarp();
    float tv = 0.f, vv = 0.f;
    for (int l = 0; l < 16; l++) {
        float o = O[l * 32 + t];
        tv += u[l] * o;
        vv += o;
    }
    tm[t] = tv; vm[t] = vv;
    __syncwarp();
    float gh = 16.f * brel2[t];
    for (int cc = 0; cc < 32; cc++)
        gh += tm[cc] * Wrel2[t * 32 + cc] + vm[cc] * Wroot2[t * 32 + cc];
    gm[t] = gh;
    __syncwarp();
    float zz = b2[t];
    for (int cc = 0; cc < 32; cc++) zz += gm[cc] * W2[t * 32 + cc];
    zm[t] = fmaxf(zz, 0.f);
    __syncwarp();
    if (t < OUTC) {
        float lo = b3[t];
        for (int cc = 0; cc < 32; cc++) lo += zm[cc] * W3[t * 32 + cc];
        lg[t] = lo;
    }
    __syncwarp();
    if (t == 0) {
        float m = -1e30f;
        for (int o = 0; o < OUTC; o++) m = fmaxf(m, lg[o]);
        float ssum = 0.f;
        for (int o = 0; o < OUTC; o++) ssum += expf(lg[o] - m);
        bc[0] = m; bc[1] = logf(ssum);
    }
    __syncwarp();
    if (t < OUTC) out[g * OUTC + t] = lg[t] - bc[0] - bc[1];
}

// ---------------- launch ----------------
extern "C" void kernel_launch(void* const* d_in, const int* in_sizes, int n_in,
                              void* d_out, int out_size) {
    const float* x      = (const float*)d_in[0];
    const float* W1     = (const float*)d_in[1];
    const float* b1     = (const float*)d_in[2];
    const float* Wrel1  = (const float*)d_in[3];
    const float* brel1  = (const float*)d_in[4];
    const float* Wroot1 = (const float*)d_in[5];
    const float* Wp     = (const float*)d_in[6];
    const float* bp     = (const float*)d_in[7];
    const float* Wrel2  = (const float*)d_in[8];
    const float* brel2  = (const float*)d_in[9];
    const float* Wroot2 = (const float*)d_in[10];
    const float* W2     = (const float*)d_in[11];
    const float* b2     = (const float*)d_in[12];
    const float* W3     = (const float*)d_in[13];
    const float* b3     = (const float*)d_in[14];
    const int*   ei     = (const int*)d_in[15];
    float* out = (float*)d_out;

    k_zero<<<256, 256>>>(out);
    k_hist<<<1024, 256>>>((const int4*)ei);
    k_lin1<<<2048, 256>>>((const float4*)x, (const float4*)W1, b1);
    k_scan1<<<64, 1024>>>();
    k_scan2<<<1, 64>>>();
    k_scan3<<<64, 1024>>>();
    k_scatter<<<1024, 256>>>(ei);
    k_conv<<<1024, 256>>>(Wrel1, brel1, Wroot1, Wp, bp);
    k_pool<<<512, 256>>>();
    k_final<<<64, 32>>>(Wrel2, brel2, Wroot2, W2, b2, W3, b3, out);
}

// round 17
// speedup vs baseline: 1.0403x; 1.0403x over previous
#include <cuda_runtime.h>
#include <math.h>

// Problem constants (fixed shapes per reference)
#define Bg   64
#define Nn   1024
#define TOT  65536      // Bg*Nn
#define NE   2097152
#define INC  128
#define HID  32
#define KK   16
#define OUTC 10

// ---------------- device scratch (no allocation allowed) ----------------
__device__ float d_h1[TOT * HID];      // after lin1
__device__ float d_h [TOT * HID];      // after conv1
__device__ float d_s [TOT * KK];       // softmax assignments
__device__ int   d_deg[TOT];           // out-degree == d_flat
__device__ int   d_rowstart[TOT];
__device__ int   d_cursor[TOT];
__device__ int   d_csr[NE];            // dst sorted by src (CSR)
__device__ int   d_bsum[64];           // per-block degree totals for scan
__device__ float d_outp[Bg * KK * HID];   // s^T h
__device__ float d_oadj[Bg * KK * KK];    // s^T adj s
__device__ float d_ssg [Bg * KK * KK];    // s^T s
__device__ float d_den [Bg];              // sum d*s^2

__device__ __forceinline__ float warp_sum(float v) {
    #pragma unroll
    for (int o = 16; o; o >>= 1) v += __shfl_xor_sync(0xffffffffu, v, o);
    return v;
}

// ---------------- zero scratch + output ----------------
__global__ void k_zero(float* __restrict__ out) {
    int i = blockIdx.x * blockDim.x + threadIdx.x;   // 256*256 = 65536
    d_deg[i] = 0;
    if (i < Bg * KK * HID) d_outp[i] = 0.f;
    if (i < Bg * KK * KK)  { d_oadj[i] = 0.f; d_ssg[i] = 0.f; }
    if (i < Bg)            d_den[i] = 0.f;
    if (i < Bg * OUTC + 2) out[i] = 0.f;
}

// ---------------- merged: h1 = x@W1^T+b1 (blocks 0..2047) + degree hist ----
__global__ void k_mid(const float4* __restrict__ x4, const float4* __restrict__ W1f4,
                      const float* __restrict__ b1, const int4* __restrict__ ei4) {
    int b = blockIdx.x, tid = threadIdx.x;
    if (b >= 2048) {                            // histogram part
        int i = (b - 2048) * 256 + tid;         // NE/4 = 524288 threads
        int4 e = ei4[i];
        atomicAdd(&d_deg[e.x], 1);
        atomicAdd(&d_deg[e.y], 1);
        atomicAdd(&d_deg[e.z], 1);
        atomicAdd(&d_deg[e.w], 1);
        return;
    }
    __shared__ float4 Wf[32 * 32];   // [c4][o]
    __shared__ float  bs[32];
    for (int i = tid; i < 1024; i += 256) {
        int o = i & 31, c4 = i >> 5;
        Wf[c4 * 32 + o] = W1f4[o * 32 + c4];
    }
    if (tid < 32) bs[tid] = b1[tid];
    __syncthreads();
    int w = tid >> 5, lane = tid & 31;
    int nb = (b * 8 + w) * 4;   // 4 nodes per warp
    float a0 = bs[lane], a1 = a0, a2 = a0, a3 = a0;
    const float4* x0 = x4 + (size_t)nb * 32;
    #pragma unroll 8
    for (int c4 = 0; c4 < 32; c4++) {
        float4 wv = Wf[c4 * 32 + lane];
        float4 xa = x0[c4], xb = x0[32 + c4], xc = x0[64 + c4], xd = x0[96 + c4];
        a0 += xa.x * wv.x + xa.y * wv.y + xa.z * wv.z + xa.w * wv.w;
        a1 += xb.x * wv.x + xb.y * wv.y + xb.z * wv.z + xb.w * wv.w;
        a2 += xc.x * wv.x + xc.y * wv.y + xc.z * wv.z + xc.w * wv.w;
        a3 += xd.x * wv.x + xd.y * wv.y + xd.z * wv.z + xd.w * wv.w;
    }
    d_h1[(nb + 0) * 32 + lane] = a0;
    d_h1[(nb + 1) * 32 + lane] = a1;
    d_h1[(nb + 2) * 32 + lane] = a2;
    d_h1[(nb + 3) * 32 + lane] = a3;
}

// ---------------- scan phase 1: intra-block exclusive scan + block totals ---
__global__ void k_scan1() {
    __shared__ int wsum[32];
    int b = blockIdx.x, tid = threadIdx.x;
    int idx = b * 1024 + tid;
    int v = d_deg[idx];
    int lane = tid & 31, wid = tid >> 5;
    int p = v;
    #pragma unroll
    for (int o = 1; o < 32; o <<= 1) {
        int t = __shfl_up_sync(0xffffffffu, p, o);
        if (lane >= o) p += t;
    }
    if (lane == 31) wsum[wid] = p;
    __syncthreads();
    if (wid == 0) {
        int w = wsum[lane];
        #pragma unroll
        for (int o = 1; o < 32; o <<= 1) {
            int t = __shfl_up_sync(0xffffffffu, w, o);
            if (lane >= o) w += t;
        }
        wsum[lane] = w;
    }
    __syncthreads();
    int ex = p - v + (wid ? wsum[wid - 1] : 0);
    d_rowstart[idx] = ex;
    if (tid == 1023) d_bsum[b] = ex + v;
}

// ---------------- scan phase 2+3 merged: each block sums bsum[0..b-1] -------
__global__ void k_scan23() {
    __shared__ int sprev;
    int b = blockIdx.x, tid = threadIdx.x;
    if (tid < 32) {
        int x0 = (tid < b)      ? d_bsum[tid]      : 0;
        int x1 = (32 + tid < b) ? d_bsum[32 + tid] : 0;
        int s = x0 + x1;
        #pragma unroll
        for (int o = 16; o; o >>= 1) s += __shfl_xor_sync(0xffffffffu, s, o);
        if (tid == 0) sprev = s;
    }
    __syncthreads();
    int idx = b * 1024 + tid;
    int r = d_rowstart[idx] + sprev;
    d_rowstart[idx] = r;
    d_cursor[idx]   = r;
}

// ---------------- scatter dst into CSR (int4 vectorized) ----------------
__global__ void k_scatter(const int* __restrict__ ei) {
    const int4* src4 = (const int4*)ei;
    const int4* dst4 = (const int4*)(ei + NE);
    int i = blockIdx.x * blockDim.x + threadIdx.x;   // NE/4 threads
    int4 s = src4[i];
    int4 d = dst4[i];
    d_csr[atomicAdd(&d_cursor[s.x], 1)] = d.x;
    d_csr[atomicAdd(&d_cursor[s.y], 1)] = d.y;
    d_csr[atomicAdd(&d_cursor[s.z], 1)] = d.z;
    d_csr[atomicAdd(&d_cursor[s.w], 1)] = d.w;
}

// ---------------- conv1 + pool-projection + softmax (fused, warp/node) ------
// Gather (R5-proven form): 4 neighbors per warp-iteration, float4 per lane,
// 2 independent chains; 2048 blocks x 4 nodes/warp for wave balance.
__global__ void k_conv(const float* __restrict__ Wrel1, const float* __restrict__ brel1,
                       const float* __restrict__ Wroot1, const float* __restrict__ Wp,
                       const float* __restrict__ bp) {
    __shared__ float Wr[1024], Wo[1024], Wpt[512], br[32], bps[16];
    __shared__ __align__(16) float stage[8][64];
    int tid = threadIdx.x;
    for (int i = tid; i < 1024; i += 256) {
        int o = i >> 5, c = i & 31;
        Wr[c * 32 + o] = Wrel1[i];
        Wo[c * 32 + o] = Wroot1[i];
    }
    for (int i = tid; i < 512; i += 256) {
        int k = i >> 5, o = i & 31;
        Wpt[o * 16 + k] = Wp[i];
    }
    if (tid < 32) br[tid]  = brel1[tid];
    if (tid < 16) bps[tid] = bp[tid];
    __syncthreads();
    const float4* h1f4 = (const float4*)d_h1;
    int w = tid >> 5, lane = tid & 31;
    int qg = lane >> 3;            // neighbor subgroup 0..3
    int qc = lane & 7;             // float4 column 0..7
    int gw = blockIdx.x * 8 + w;   // 16384 warps, 4 nodes each
    for (int i = 0; i < 4; i++) {
        int n = gw * 4 + i;
        float h1c = d_h1[n * 32 + lane];
        int st = d_rowstart[n], len = d_deg[n];
        float4 a0 = {0.f,0.f,0.f,0.f}, a1 = {0.f,0.f,0.f,0.f};
        int j = qg;
        for (; j + 4 < len; j += 8) {           // 2 chains x 4 neighbors/warp
            int e0 = d_csr[st + j];
            int e1 = d_csr[st + j + 4];
            float4 v0 = h1f4[e0 * 8 + qc];
            float4 v1 = h1f4[e1 * 8 + qc];
            a0.x += v0.x; a0.y += v0.y; a0.z += v0.z; a0.w += v0.w;
            a1.x += v1.x; a1.y += v1.y; a1.z += v1.z; a1.w += v1.w;
        }
        if (j < len) {
            float4 v = h1f4[d_csr[st + j] * 8 + qc];
            a0.x += v.x; a0.y += v.y; a0.z += v.z; a0.w += v.w;
        }
        a0.x += a1.x; a0.y += a1.y; a0.z += a1.z; a0.w += a1.w;
        #pragma unroll
        for (int o = 8; o <= 16; o <<= 1) {     // reduce over 4 subgroups
            a0.x += __shfl_xor_sync(0xffffffffu, a0.x, o);
            a0.y += __shfl_xor_sync(0xffffffffu, a0.y, o);
            a0.z += __shfl_xor_sync(0xffffffffu, a0.z, o);
            a0.w += __shfl_xor_sync(0xffffffffu, a0.w, o);
        }
        __syncwarp();
        if (qg == 0) ((float4*)&stage[w][0])[qc] = a0;   // cols 0..31 = neighbor sum
        stage[w][32 + lane] = h1c;
        __syncwarp();
        float hv = br[lane];
        #pragma unroll
        for (int c = 0; c < 32; c++)
            hv += stage[w][c] * Wr[c * 32 + lane] + stage[w][32 + c] * Wo[c * 32 + lane];
        d_h[n * 32 + lane] = hv;
        __syncwarp();
        stage[w][lane] = hv;
        __syncwarp();
        int k = lane & 15;                 // duplicated halves
        float p = bps[k];
        #pragma unroll
        for (int o = 0; o < 32; o++) p += stage[w][o] * Wpt[o * 16 + k];
        float m = p;
        #pragma unroll
        for (int off = 8; off >= 1; off >>= 1)
            m = fmaxf(m, __shfl_xor_sync(0xffffffffu, m, off));
        float e = __expf(p - m);
        float se = e;
        #pragma unroll
        for (int off = 8; off >= 1; off >>= 1)
            se += __shfl_xor_sync(0xffffffffu, se, off);
        if (lane < 16) d_s[n * 16 + lane] = e / se;
    }
}

// ---------------- adj@s gather + per-graph reductions (register accumulators) ----
__global__ void k_pool() {
    __shared__ float wacc[8][1056];
    __shared__ __align__(16) float sst[8][16], ast[8][16];
    int tid = threadIdx.x;
    int w = tid >> 5, lane = tid & 31;
    int g = blockIdx.x >> 3;
    int nb = g * 1024 + (blockIdx.x & 7) * 128 + w * 16;   // 16 nodes per warp
    int c = lane & 15;
    int qg = lane >> 2;            // neighbor subgroup 0..7
    int qc = lane & 3;             // float4 column 0..3
    const float4* sf4 = (const float4*)d_s;
    float rout[16], radj[16], rss[16];
    #pragma unroll
    for (int k = 0; k < 16; k++) { rout[k] = 0.f; radj[k] = 0.f; rss[k] = 0.f; }
    float denp = 0.f;
    for (int i = 0; i < 16; i++) {
        int n = nb + i;
        float sv = d_s[n * 16 + c];
        int st = d_rowstart[n], len = d_deg[n];
        float4 a0 = {0.f,0.f,0.f,0.f}, a1 = {0.f,0.f,0.f,0.f};
        int j = qg;
        for (; j + 8 < len; j += 16) {          // 2 chains x 8 neighbors/warp
            int e0 = d_csr[st + j];
            int e1 = d_csr[st + j + 8];
            float4 v0 = sf4[e0 * 4 + qc];
            float4 v1 = sf4[e1 * 4 + qc];
            a0.x += v0.x; a0.y += v0.y; a0.z += v0.z; a0.w += v0.w;
            a1.x += v1.x; a1.y += v1.y; a1.z += v1.z; a1.w += v1.w;
        }
        if (j < len) {
            float4 v = sf4[d_csr[st + j] * 4 + qc];
            a0.x += v.x; a0.y += v.y; a0.z += v.z; a0.w += v.w;
        }
        a0.x += a1.x; a0.y += a1.y; a0.z += a1.z; a0.w += a1.w;
        #pragma unroll
        for (int o = 4; o <= 16; o <<= 1) {     // reduce over 8 subgroups
            a0.x += __shfl_xor_sync(0xffffffffu, a0.x, o);
            a0.y += __shfl_xor_sync(0xffffffffu, a0.y, o);
            a0.z += __shfl_xor_sync(0xffffffffu, a0.z, o);
            a0.w += __shfl_xor_sync(0xffffffffu, a0.w, o);
        }
        float hl = d_h[n * 32 + lane];
        __syncwarp();
        if (lane < 4) ((float4*)&ast[w][0])[qc] = a0;   // adj@s row (16 floats)
        if (lane < 16) sst[w][lane] = sv;
        __syncwarp();
        float av = (lane < 16) ? ast[w][lane] : 0.f;
        #pragma unroll
        for (int k = 0; k < 16; k++) {
            float sk = sst[w][k];
            rout[k] += sk * hl;
            radj[k] += sk * av;
            rss[k]  += sk * sv;
        }
        if (lane < 16) denp += (float)len * sv * sv;
        __syncwarp();
    }
    float* wa = wacc[w];
    #pragma unroll
    for (int k = 0; k < 16; k++) wa[k * 32 + lane] = rout[k];
    if (lane < 16) {
        #pragma unroll
        for (int k = 0; k < 16; k++) {
            wa[512 + k * 16 + lane] = radj[k];
            wa[768 + k * 16 + lane] = rss[k];
        }
    }
    float dv = (lane < 16) ? denp : 0.f;
    dv = warp_sum(dv);
    if (lane == 0) wa[1024] = dv;
    __syncthreads();
    for (int idx = tid; idx < 1025; idx += 256) {
        float v = 0.f;
        #pragma unroll
        for (int ww = 0; ww < 8; ww++) v += wacc[ww][idx];
        if (idx < 512)       atomicAdd(&d_outp[g * 512 + idx], v);
        else if (idx < 768)  atomicAdd(&d_oadj[g * 256 + (idx - 512)], v);
        else if (idx < 1024) atomicAdd(&d_ssg [g * 256 + (idx - 768)], v);
        else                 atomicAdd(&d_den[g], v);
    }
}

// ---------------- per-graph tail ----------------
__global__ void k_final(const float* __restrict__ Wrel2, const float* __restrict__ brel2,
                        const float* __restrict__ Wroot2, const float* __restrict__ W2,
                        const float* __restrict__ b2, const float* __restrict__ W3,
                        const float* __restrict__ b3, float* __restrict__ out) {
    int g = blockIdx.x, t = threadIdx.x;   // 32 threads
    __shared__ float A[256], S[256], O[512], di[16], u[16];
    __shared__ float tm[32], vm[32], gm[32], zm[32], lg[10], bc[2];
    for (int i = t; i < 256; i += 32) { A[i] = d_oadj[g * 256 + i]; S[i] = d_ssg[g * 256 + i]; }
    for (int i = t; i < 512; i += 32)   O[i] = d_outp[g * 512 + i];
    __syncwarp();
    float num = (t < 16) ? A[t * 17] : 0.f;
    num = warp_sum(num);
    float den = d_den[g];
    float p2 = 0.f;
    for (int i = t; i < 256; i += 32) p2 += S[i] * S[i];
    float nrm = sqrtf(warp_sum(p2));
    float p3 = 0.f;
    for (int i = t; i < 256; i += 32) {
        float dvv = S[i] / nrm - (((i >> 4) == (i & 15)) ? 0.25f : 0.f);
        p3 += dvv * dvv;
    }
    float ortho = sqrtf(warp_sum(p3));
    if (t == 0) {
        atomicAdd(out + Bg * OUTC,     -(num / den) * (1.f / Bg));
        atomicAdd(out + Bg * OUTC + 1, ortho * (1.f / Bg));
    }
    if (t < 16) A[t * 17] = 0.f;
    __syncwarp();
    if (t < 16) {
        float r = 0.f;
        for (int j = 0; j < 16; j++) r += A[t * 16 + j];
        di[t] = sqrtf(r) + 1e-15f;
    }
    __syncwarp();
    if (t < 16) {
        float uu = 0.f;
        for (int k = 0; k < 16; k++) uu += A[k * 16 + t] / di[k];
        u[t] = uu / di[t];
    }
    __syncwarp();
    float tv = 0.f, vv = 0.f;
    for (int l = 0; l < 16; l++) {
        float o = O[l * 32 + t];
        tv += u[l] * o;
        vv += o;
    }
    tm[t] = tv; vm[t] = vv;
    __syncwarp();
    float gh = 16.f * brel2[t];
    for (int cc = 0; cc < 32; cc++)
        gh += tm[cc] * Wrel2[t * 32 + cc] + vm[cc] * Wroot2[t * 32 + cc];
    gm[t] = gh;
    __syncwarp();
    float zz = b2[t];
    for (int cc = 0; cc < 32; cc++) zz += gm[cc] * W2[t * 32 + cc];
    zm[t] = fmaxf(zz, 0.f);
    __syncwarp();
    if (t < OUTC) {
        float lo = b3[t];
        for (int cc = 0; cc < 32; cc++) lo += zm[cc] * W3[t * 32 + cc];
        lg[t] = lo;
    }
    __syncwarp();
    if (t == 0) {
        float m = -1e30f;
        for (int o = 0; o < OUTC; o++) m = fmaxf(m, lg[o]);
        float ssum = 0.f;
        for (int o = 0; o < OUTC; o++) ssum += expf(lg[o] - m);
        bc[0] = m; bc[1] = logf(ssum);
    }
    __syncwarp();
    if (t < OUTC) out[g * OUTC + t] = lg[t] - bc[0] - bc[1];
}

// ---------------- launch ----------------
extern "C" void kernel_launch(void* const* d_in, const int* in_sizes, int n_in,
                              void* d_out, int out_size) {
    const float* x      = (const float*)d_in[0];
    const float* W1     = (const float*)d_in[1];
    const float* b1     = (const float*)d_in[2];
    const float* Wrel1  = (const float*)d_in[3];
    const float* brel1  = (const float*)d_in[4];
    const float* Wroot1 = (const float*)d_in[5];
    const float* Wp     = (const float*)d_in[6];
    const float* bp     = (const float*)d_in[7];
    const float* Wrel2  = (const float*)d_in[8];
    const float* brel2  = (const float*)d_in[9];
    const float* Wroot2 = (const float*)d_in[10];
    const float* W2     = (const float*)d_in[11];
    const float* b2     = (const float*)d_in[12];
    const float* W3     = (const float*)d_in[13];
    const float* b3     = (const float*)d_in[14];
    const int*   ei     = (const int*)d_in[15];
    float* out = (float*)d_out;

    k_zero<<<256, 256>>>(out);
    k_mid<<<4096, 256>>>((const float4*)x, (const float4*)W1, b1, (const int4*)ei);
    k_scan1<<<64, 1024>>>();
    k_scan23<<<64, 1024>>>();
    k_scatter<<<2048, 256>>>(ei);
    k_conv<<<2048, 256>>>(Wrel1, brel1, Wroot1, Wp, bp);
    k_pool<<<512, 256>>>();
    k_final<<<64, 32>>>(Wrel2, brel2, Wroot2, W2, b2, W3, b3, out);
}